// round 10
// baseline (speedup 1.0000x reference)
#include <cuda_runtime.h>
#include <stdint.h>

// AND-tree over last dim of (ROWS, 1024) binary float matrix.
// out[row] = 1.0f iff all 1024 elements == 1.0f (bit pattern 0x3F800000).
//
// Key change vs all prior MEASURED rounds: STAGGERED probe offsets.
// Previously every row was probed at byte offset 0 -> all 65536 probed
// addresses had bits [0:12) == 0, freezing L2-slice hash inputs (bits
// 8,10,11) and HBM channel/bank-select bits below bit 12 -> severe address
// aliasing, ~17% of DRAM peak. Probing row r at byte offset (r&31)*128
// sweeps bits [7:12) through all values, spreading probes across L2 slices
// and DRAM banks.
//
// Probe = 64B (16 elements) -> survival prob 2^-16 -> ~1 survivor chip-wide.
// Survivors resolved warp-cooperatively in one extra DRAM round (full-row
// scan, superset of the probe window -> exact).
// (Re-submission of R8: previous attempt died to a container infra failure
// before execution; the experiment is still unrun.)

static constexpr int ROW_U4 = 1024 / 4;            // 256 uint4 per row
static constexpr unsigned ONE_BITS = 0x3F800000u;  // bit pattern of 1.0f
static constexpr int THREADS = 512;

__device__ __forceinline__ bool all_ones(uint4 v) {
    return v.x == ONE_BITS && v.y == ONE_BITS && v.z == ONE_BITS && v.w == ONE_BITS;
}

__global__ __launch_bounds__(THREADS) void vec_and_tree_kernel(
    const uint4* __restrict__ x, float* __restrict__ out, int rows)
{
    int row = blockIdx.x * THREADS + threadIdx.x;
    row = row < rows ? row : rows - 1;       // branchless clamp (benign dup)
    const int lane = threadIdx.x & 31;

    const uint4* rp = x + (size_t)row * ROW_U4;

    // Staggered probe: 128B-aligned window at uint4 offset (row&31)*8,
    // i.e. byte offset (row&31)*128. Sweeps address bits [7:12) across rows.
    const int off = (row & 31) * 8;
    uint4 a = rp[off + 0], b = rp[off + 1], c = rp[off + 2], d = rp[off + 3];
    bool ok = all_ones(a) & all_ones(b) & all_ones(c) & all_ones(d);

    // Survivors (prob 2^-16/row): warp-cooperative full-row check, one round.
    unsigned surv = __ballot_sync(0xFFFFFFFFu, ok);
    while (surv) {
        const int l = __ffs(surv) - 1;
        surv &= surv - 1;
        const int srow = __shfl_sync(0xFFFFFFFFu, row, l);
        const uint4* sp = x + (size_t)srow * ROW_U4;

        bool lok = true;
        #pragma unroll
        for (int i = 0; i < ROW_U4 / 32; i++) {     // 8 independent loads, MLP=8
            lok &= all_ones(__ldcs(sp + i * 32 + lane));
        }
        const bool rok = __all_sync(0xFFFFFFFFu, lok);
        if (lane == l) ok = rok;
    }

    out[row] = ok ? 1.0f : 0.0f;
}

extern "C" void kernel_launch(void* const* d_in, const int* in_sizes, int n_in,
                              void* d_out, int out_size)
{
    const uint4* x = (const uint4*)d_in[0];  // float32 bits reinterpreted
    float* out = (float*)d_out;

    const int rows = out_size;                              // 65536
    const int blocks = (rows + THREADS - 1) / THREADS;      // 128

    vec_and_tree_kernel<<<blocks, THREADS>>>(x, out, rows);
}

// round 14
// speedup vs baseline: 1.0047x; 1.0047x over previous
#include <cuda_runtime.h>
#include <stdint.h>

// AND-tree over last dim of (ROWS, 1024) binary float matrix.
// out[row] = 1.0f iff all 1024 elements == 1.0f (bit pattern 0x3F800000).
//
// R11 experiment: single-SECTOR probe with streaming loads.
// Evidence R2-R10: every variant moves exactly 128B x 65536 rows (~8.4MB)
// at ~1.38TB/s regardless of requested probe size (even 16B requests pulled
// 128B/row) -> memory system promotes each probed row to a full-line fetch,
// and the kernel is limited by a per-LINE rate (~12ns/line/channel, bus 17%
// busy), not bandwidth. This round probes exactly ONE 32B sector per row via
// __ldcs (ld.global.cs: streaming, evict-first, no-promote hint) to test
// whether the limit is per-request/promotion (expect ~4x fewer requests ->
// ~3.5-4.5us) or per-DRAM-activation (expect neutral ~6.6us = hard floor).
//
// Probe = 8 elements -> survival 2^-8 -> ~256 survivors chip-wide, resolved
// warp-cooperatively (full-row scan, superset of probe -> exact).

static constexpr int ROW_U4 = 1024 / 4;            // 256 uint4 per row
static constexpr unsigned ONE_BITS = 0x3F800000u;  // bit pattern of 1.0f
static constexpr int THREADS = 512;

__device__ __forceinline__ bool all_ones(uint4 v) {
    return v.x == ONE_BITS && v.y == ONE_BITS && v.z == ONE_BITS && v.w == ONE_BITS;
}

__global__ __launch_bounds__(THREADS) void vec_and_tree_kernel(
    const uint4* __restrict__ x, float* __restrict__ out, int rows)
{
    int row = blockIdx.x * THREADS + threadIdx.x;
    row = row < rows ? row : rows - 1;       // branchless clamp (benign dup)
    const int lane = threadIdx.x & 31;

    const uint4* rp = x + (size_t)row * ROW_U4;

    // Probe: ONE 32B sector (two consecutive uint4, 32B-aligned since the
    // stagger offset is a multiple of 8 uint4 = 128B). Streaming loads to
    // suppress line promotion / L2 pollution. Stagger sweeps addr bits [7:12).
    const int off = (row & 31) * 8;
    uint4 a = __ldcs(rp + off);
    uint4 b = __ldcs(rp + off + 1);
    bool ok = all_ones(a) & all_ones(b);

    // Survivors (prob 2^-8/row, ~1 per 8 warps): warp-cooperative full-row
    // check, one extra parallel DRAM round per surviving row.
    unsigned surv = __ballot_sync(0xFFFFFFFFu, ok);
    while (surv) {
        const int l = __ffs(surv) - 1;
        surv &= surv - 1;
        const int srow = __shfl_sync(0xFFFFFFFFu, row, l);
        const uint4* sp = x + (size_t)srow * ROW_U4;

        bool lok = true;
        #pragma unroll
        for (int i = 0; i < ROW_U4 / 32; i++) {     // 8 independent loads, MLP=8
            lok &= all_ones(__ldcs(sp + i * 32 + lane));
        }
        const bool rok = __all_sync(0xFFFFFFFFu, lok);
        if (lane == l) ok = rok;
    }

    out[row] = ok ? 1.0f : 0.0f;
}

extern "C" void kernel_launch(void* const* d_in, const int* in_sizes, int n_in,
                              void* d_out, int out_size)
{
    const uint4* x = (const uint4*)d_in[0];  // float32 bits reinterpreted
    float* out = (float*)d_out;

    const int rows = out_size;                              // 65536
    const int blocks = (rows + THREADS - 1) / THREADS;      // 128

    vec_and_tree_kernel<<<blocks, THREADS>>>(x, out, rows);
}